// round 1
// baseline (speedup 1.0000x reference)
#include <cuda_runtime.h>

// Problem constants: X[8,256,128], W1[128,128], W2[128,128], v[128] -> out[8,256,256]
#define BB   8
#define DD   256
#define DIM  128
#define ROWS 2048            // BB*DD

// Scratch (allocation-free rule: __device__ globals)
__device__ float g_Ea [ROWS * DIM];        // exp(2*A[b,d,m]), layout [row][m]
__device__ float g_EcT[BB * DIM * DD];     // exp(2*C[b,d,m]) TRANSPOSED: [b][m][d]

// ---------------------------------------------------------------------------
// Kernel 1: A = X@W1^T, C = X@W2^T, store Ea = exp(2A) (row-major),
//           EcT = exp(2C) transposed ([b][m][k]) so kernel 2 stages coalesced.
// Block = 8 rows of X, 256 threads. W1,W2 staged in SMEM (stride 132 floats:
// conflict-free per-phase float4 reads: bank = (4m + 4k4) mod 32).
// ---------------------------------------------------------------------------
#define W_STRIDE 132
#define K1_SMEM ((2 * DIM * W_STRIDE + 8 * DIM) * 4)

__global__ void __launch_bounds__(256) k1_gemm_exp(
    const float* __restrict__ X,
    const float* __restrict__ W1,
    const float* __restrict__ W2)
{
    extern __shared__ float sm[];
    float* W1s = sm;                         // 128 x 132
    float* W2s = sm + DIM * W_STRIDE;        // 128 x 132
    float* Xs  = sm + 2 * DIM * W_STRIDE;    // 8 x 128

    const int t       = threadIdx.x;
    const int rowbase = blockIdx.x * 8;      // global row in [0, 2048)

    // Stage W1/W2: 4096 float4 each, coalesced loads, conflict-free stores.
    #pragma unroll
    for (int i = t; i < DIM * 32; i += 256) {
        int m  = i >> 5;
        int k4 = i & 31;
        float4 a = ((const float4*)W1)[i];
        float4 b = ((const float4*)W2)[i];
        *(float4*)&W1s[m * W_STRIDE + k4 * 4] = a;
        *(float4*)&W2s[m * W_STRIDE + k4 * 4] = b;
    }
    // Stage 8 X rows (1024 floats = 256 float4)
    ((float4*)Xs)[t] = ((const float4*)X)[rowbase * 32 + t];
    __syncthreads();

    const int mat = t >> 7;          // 0 -> W1/Ea, 1 -> W2/EcT
    const int m   = t & 127;
    const float* Ws = mat ? W2s : W1s;

    float acc[8];
    #pragma unroll
    for (int r = 0; r < 8; r++) acc[r] = 0.0f;

    #pragma unroll 8
    for (int k4 = 0; k4 < 32; k4++) {
        float4 w = *(const float4*)&Ws[m * W_STRIDE + k4 * 4];
        #pragma unroll
        for (int r = 0; r < 8; r++) {
            float4 x = *(const float4*)&Xs[r * DIM + k4 * 4];
            acc[r] = fmaf(w.x, x.x, acc[r]);
            acc[r] = fmaf(w.y, x.y, acc[r]);
            acc[r] = fmaf(w.z, x.z, acc[r]);
            acc[r] = fmaf(w.w, x.w, acc[r]);
        }
    }

    if (mat == 0) {
        #pragma unroll
        for (int r = 0; r < 8; r++)
            g_Ea[(rowbase + r) * DIM + m] = __expf(2.0f * acc[r]);
    } else {
        const int b  = rowbase >> 8;     // 8 rows share one batch (8 | 256)
        const int d0 = rowbase & 255;
        #pragma unroll
        for (int r = 0; r < 8; r++)
            g_EcT[(b * DIM + m) * DD + (d0 + r)] = __expf(2.0f * acc[r]);
    }
}

// ---------------------------------------------------------------------------
// Kernel 2: out[b,j,k] = Vsum - 2 * sum_m v[m] / (Ea[b,j,m]*Ec[b,k,m] + 1)
// Block = (b, 8 j-rows). Full EcT[b] slice (128KB) staged in SMEM once per
// block -> each thread owns one k, accumulates 8 j's privately (no shuffles).
// Per element: 1 FFMA + 1 MUFU.RCP + 1 FFMA  => MUFU-bound (~28K cyc chip).
// ---------------------------------------------------------------------------
#define K2_SMEM ((DIM * DD + 8 * DIM + DIM) * 4)

__global__ void __launch_bounds__(256) k2_pairwise(
    const float* __restrict__ v,
    float* __restrict__ out)
{
    extern __shared__ float sm[];
    float* EcTs = sm;                   // [m][k] : 128 x 256, stride 256
    float* Eas  = sm + DIM * DD;        // [j][m] : 8 x 128
    float* vs   = Eas + 8 * DIM;        // 128

    const int t  = threadIdx.x;
    const int b  = blockIdx.x >> 5;
    const int j0 = (blockIdx.x & 31) << 3;

    // Stage EcT[b] (8192 float4, coalesced LDG + linear STS, conflict-free)
    const float4* src  = (const float4*)(g_EcT + (size_t)b * DIM * DD);
    float4*       dstv = (float4*)EcTs;
    #pragma unroll
    for (int i = t; i < DIM * DD / 4; i += 256) dstv[i] = src[i];

    // Stage 8 Ea rows (256 float4) and v (32 float4)
    ((float4*)Eas)[t] = ((const float4*)(g_Ea + (size_t)(b * DD + j0) * DIM))[t];
    if (t < 32) ((float4*)vs)[t] = ((const float4*)v)[t];
    __syncthreads();

    float Vsum = 0.0f;
    #pragma unroll
    for (int m4 = 0; m4 < 32; m4++) {
        float4 vv = ((const float4*)vs)[m4];
        Vsum += (vv.x + vv.y) + (vv.z + vv.w);
    }

    const int k = t;   // thread t owns column k; lanes = consecutive k
    float acc[8];
    #pragma unroll
    for (int j = 0; j < 8; j++) acc[j] = 0.0f;

    #pragma unroll 4
    for (int m = 0; m < 128; m++) {
        float ec = EcTs[m * DD + k];    // bank = lane: conflict-free
        float vm = vs[m];               // uniform broadcast
        #pragma unroll
        for (int j = 0; j < 8; j++) {
            float q = fmaf(Eas[j * DIM + m], ec, 1.0f);
            float r;
            asm("rcp.approx.f32 %0, %1;" : "=f"(r) : "f"(q));
            acc[j] = fmaf(vm, r, acc[j]);
        }
    }

    float* orow = out + ((size_t)(b * DD + j0) * DD) + k;
    #pragma unroll
    for (int j = 0; j < 8; j++)
        orow[(size_t)j * DD] = fmaf(-2.0f, acc[j], Vsum);
}

// ---------------------------------------------------------------------------
extern "C" void kernel_launch(void* const* d_in, const int* in_sizes, int n_in,
                              void* d_out, int out_size)
{
    const float* X  = (const float*)d_in[0];
    const float* W1 = (const float*)d_in[1];
    const float* W2 = (const float*)d_in[2];
    const float* v  = (const float*)d_in[3];
    float* out      = (float*)d_out;

    cudaFuncSetAttribute(k1_gemm_exp,
                         cudaFuncAttributeMaxDynamicSharedMemorySize, K1_SMEM);
    cudaFuncSetAttribute(k2_pairwise,
                         cudaFuncAttributeMaxDynamicSharedMemorySize, K2_SMEM);

    k1_gemm_exp<<<ROWS / 8, 256, K1_SMEM>>>(X, W1, W2);
    k2_pairwise<<<BB * (DD / 8), 256, K2_SMEM>>>(v, out);
}

// round 2
// speedup vs baseline: 1.3696x; 1.3696x over previous
#include <cuda_runtime.h>

typedef unsigned long long ull;

// Problem constants: X[8,256,128], W1[128,128], W2[128,128], v[128] -> out[8,256,256]
#define BB   8
#define DD   256
#define DIM  128
#define ROWS 2048            // BB*DD

// Scratch (allocation-free rule: __device__ globals)
__device__ float g_Ea [ROWS * DIM];        // exp(2*A[b,d,m])  layout [row][m]
__device__ float g_EcT[BB * DIM * DD];     // exp(2*C[b,d,m])  TRANSPOSED [b][m][k]

// ---- packed f32x2 helpers (Blackwell sm_100+) ------------------------------
__device__ __forceinline__ ull fma2(ull a, ull b, ull c) {
    ull d; asm("fma.rn.f32x2 %0,%1,%2,%3;" : "=l"(d) : "l"(a), "l"(b), "l"(c)); return d;
}
__device__ __forceinline__ ull mul2(ull a, ull b) {
    ull d; asm("mul.rn.f32x2 %0,%1,%2;" : "=l"(d) : "l"(a), "l"(b)); return d;
}
__device__ __forceinline__ ull dup2(float x) {
    ull d; asm("mov.b64 %0,{%1,%1};" : "=l"(d) : "f"(x)); return d;
}
__device__ __forceinline__ float2 unpk(ull a) {
    float2 r; asm("mov.b64 {%0,%1},%2;" : "=f"(r.x), "=f"(r.y) : "l"(a)); return r;
}
__device__ __forceinline__ ull pk(float x, float y) {
    ull d; asm("mov.b64 %0,{%1,%2};" : "=l"(d) : "f"(x), "f"(y)); return d;
}
__device__ __forceinline__ float frcp(float x) {
    float r; asm("rcp.approx.f32 %0,%1;" : "=f"(r) : "f"(x)); return r;
}

// ---------------------------------------------------------------------------
// Kernel 1: one (16-row tile, one matrix) per block -> 256 blocks, 76KB smem,
// occ=2 => all 256 blocks co-resident (single wave).
// mat==0: Ea = exp(2 * X@W1^T) row-major.  mat==1: EcT = exp(2 * X@W2^T) [b][m][k].
// ---------------------------------------------------------------------------
#define W_STRIDE 132
#define K1_SMEM ((DIM * W_STRIDE + 16 * DIM) * 4)

__global__ void __launch_bounds__(256, 2) k1_gemm_exp(
    const float* __restrict__ X,
    const float* __restrict__ W1,
    const float* __restrict__ W2)
{
    extern __shared__ float sm[];
    float* Ws = sm;                        // 128 x 132 (conflict-free float4 reads)
    float* Xs = sm + DIM * W_STRIDE;       // 16 x 128

    const int t       = threadIdx.x;
    const int mat     = blockIdx.x & 1;
    const int rowbase = (blockIdx.x >> 1) * 16;
    const float* W = mat ? W2 : W1;

    // Stage W (4096 float4) and 16 X rows (512 float4), coalesced.
    #pragma unroll
    for (int i = t; i < DIM * 32; i += 256) {
        int m  = i >> 5;
        int k4 = i & 31;
        *(float4*)&Ws[m * W_STRIDE + k4 * 4] = ((const float4*)W)[i];
    }
    #pragma unroll
    for (int i = t; i < 512; i += 256)
        ((float4*)Xs)[i] = ((const float4*)X)[rowbase * 32 + i];
    __syncthreads();

    const int m  = t & 127;
    const int r0 = (t >> 7) * 8;           // rows r0..r0+7 of this tile

    float acc[8];
    #pragma unroll
    for (int r = 0; r < 8; r++) acc[r] = 0.0f;

    #pragma unroll 8
    for (int k4 = 0; k4 < 32; k4++) {
        float4 w = *(const float4*)&Ws[m * W_STRIDE + k4 * 4];
        #pragma unroll
        for (int r = 0; r < 8; r++) {
            float4 x = *(const float4*)&Xs[(r0 + r) * DIM + k4 * 4];
            acc[r] = fmaf(w.x, x.x, acc[r]);
            acc[r] = fmaf(w.y, x.y, acc[r]);
            acc[r] = fmaf(w.z, x.z, acc[r]);
            acc[r] = fmaf(w.w, x.w, acc[r]);
        }
    }

    if (mat == 0) {
        #pragma unroll
        for (int r = 0; r < 8; r++)
            g_Ea[(size_t)(rowbase + r0 + r) * DIM + m] = __expf(2.0f * acc[r]);
    } else {
        const int b  = rowbase >> 8;       // 16 | 256, tile stays in one batch
        const int d0 = (rowbase & 255) + r0;
        #pragma unroll
        for (int r = 0; r < 8; r++)
            g_EcT[(size_t)(b * DIM + m) * DD + (d0 + r)] = __expf(2.0f * acc[r]);
    }
}

// ---------------------------------------------------------------------------
// Kernel 2: out[b,j,k] = Vsum - 2 * sum_m v[m] / (Ea[b,j,m]*Ec[b,k,m] + 1)
// Per block: 8 j-rows x 256 k (thread = k). Ec staged in two 64KB m-halves
// (69KB smem => 2 blocks/SM => single co-resident wave, 16 warps/SM).
// m processed in PAIRS (one rcp per 2 m via rational combine), j in packed
// f32x2 lanes (EaT staged [m][j] so j-pairs are native LDS.64 loads).
// Per 2m x 8j (16 elems): 24 FMA2 + 8 RCP + 10 MOV + ~12 LDS.
// ---------------------------------------------------------------------------
#define K2_SMEM ((64 * DD + DIM * 8 + 64 * 4) * 4)

__global__ void __launch_bounds__(256, 2) k2_pairwise(
    const float* __restrict__ v,
    float* __restrict__ out)
{
    extern __shared__ float sm[];
    float*  Ecs = sm;                        // [64][256] current m-half
    float*  EaT = sm + 64 * DD;              // [128][8]  (m-major, j adjacent)
    float4* vs4 = (float4*)(EaT + DIM * 8);  // [64] = (v0,v0,v1,v1) per m-pair

    const int t  = threadIdx.x;
    const int b  = blockIdx.x >> 5;
    const int j0 = (blockIdx.x & 31) << 3;

    // Stage EaT (transpose 8x128 -> [m][j]); conflicts negligible (once).
    #pragma unroll
    for (int it = 0; it < 4; it++) {
        int i = t + it * 256;
        int j = i >> 7, m = i & 127;
        EaT[m * 8 + j] = g_Ea[(size_t)(b * DD + j0 + j) * DIM + m];
    }
    // Stage duplicated v pairs.
    if (t < 64) {
        float v0 = v[2 * t], v1 = v[2 * t + 1];
        vs4[t] = make_float4(v0, v0, v1, v1);
    }
    // Stage Ec half 0 (coalesced 64KB).
    {
        const float4* src = (const float4*)(g_EcT + (size_t)b * DIM * DD);
        #pragma unroll
        for (int i = t; i < 64 * DD / 4; i += 256) ((float4*)Ecs)[i] = src[i];
    }
    __syncthreads();

    float Vsum = 0.0f;
    #pragma unroll 8
    for (int m2 = 0; m2 < 64; m2++) { float4 q = vs4[m2]; Vsum += q.x + q.z; }

    const int k = t;
    const ull ONE2 = dup2(1.0f);
    ull acc[4];
    #pragma unroll
    for (int p = 0; p < 4; p++) acc[p] = dup2(0.0f);

    #pragma unroll
    for (int h = 0; h < 2; h++) {
        if (h == 1) {
            __syncthreads();   // all warps done with half 0
            const float4* src = (const float4*)(g_EcT + (size_t)b * DIM * DD + 64 * DD);
            #pragma unroll
            for (int i = t; i < 64 * DD / 4; i += 256) ((float4*)Ecs)[i] = src[i];
            __syncthreads();
        }
        #pragma unroll 4
        for (int m2l = 0; m2l < 32; m2l++) {
            const int mg = h * 64 + 2 * m2l;      // global even m of the pair
            float ec0 = Ecs[(2 * m2l) * DD + k];      // bank=lane, conflict-free
            float ec1 = Ecs[(2 * m2l + 1) * DD + k];
            ull ecc0 = dup2(ec0);
            ull ecc1 = dup2(ec1);
            ulonglong2 vv = *(const ulonglong2*)(vs4 + h * 32 + m2l); // (v0v0,v1v1)
            const ull* eap0 = (const ull*)&EaT[mg * 8];        // j-pairs, uniform
            const ull* eap1 = (const ull*)&EaT[(mg + 1) * 8];
            #pragma unroll
            for (int p = 0; p < 4; p++) {
                ull q0  = fma2(eap0[p], ecc0, ONE2);   // Ea(m0)*Ec(m0)+1
                ull q1  = fma2(eap1[p], ecc1, ONE2);   // Ea(m1)*Ec(m1)+1
                ull den = mul2(q0, q1);
                ull num = mul2(vv.x, q1);
                num     = fma2(vv.y, q0, num);         // v0*q1 + v1*q0
                float2 d2 = unpk(den);
                ull r   = pk(frcp(d2.x), frcp(d2.y));  // 1 rcp per 2 m
                acc[p]  = fma2(num, r, acc[p]);
            }
        }
    }

    float* orow = out + ((size_t)(b * DD + j0) * DD) + k;
    #pragma unroll
    for (int p = 0; p < 4; p++) {
        float2 a2 = unpk(acc[p]);
        orow[(size_t)(2 * p)     * DD] = fmaf(-2.0f, a2.x, Vsum);
        orow[(size_t)(2 * p + 1) * DD] = fmaf(-2.0f, a2.y, Vsum);
    }
}

// ---------------------------------------------------------------------------
extern "C" void kernel_launch(void* const* d_in, const int* in_sizes, int n_in,
                              void* d_out, int out_size)
{
    const float* X  = (const float*)d_in[0];
    const float* W1 = (const float*)d_in[1];
    const float* W2 = (const float*)d_in[2];
    const float* v  = (const float*)d_in[3];
    float* out      = (float*)d_out;

    cudaFuncSetAttribute(k1_gemm_exp,
                         cudaFuncAttributeMaxDynamicSharedMemorySize, K1_SMEM);
    cudaFuncSetAttribute(k2_pairwise,
                         cudaFuncAttributeMaxDynamicSharedMemorySize, K2_SMEM);

    k1_gemm_exp<<<(ROWS / 16) * 2, 256, K1_SMEM>>>(X, W1, W2);
    k2_pairwise<<<BB * (DD / 8), 256, K2_SMEM>>>(v, out);
}

// round 3
// speedup vs baseline: 1.5620x; 1.1405x over previous
#include <cuda_runtime.h>

typedef unsigned long long ull;

// Problem: X[8,256,128], W1[128,128], W2[128,128], v[128] -> out[8,256,256]
#define BB   8
#define DD   256
#define DIM  128
#define ROWS 2048

// Scratch (__device__ globals; EcT padded so k2's prefetch may over-read safely)
__device__ float g_Ea [ROWS * DIM];              // exp(2*A)  [row][m]
__device__ float g_EcT[BB * DIM * DD + 1024];    // exp(2*C)  transposed [b][m][k]

// ---- packed f32x2 helpers (Blackwell) --------------------------------------
__device__ __forceinline__ ull fma2(ull a, ull b, ull c) {
    ull d; asm("fma.rn.f32x2 %0,%1,%2,%3;" : "=l"(d) : "l"(a), "l"(b), "l"(c)); return d;
}
__device__ __forceinline__ ull mul2(ull a, ull b) {
    ull d; asm("mul.rn.f32x2 %0,%1,%2;" : "=l"(d) : "l"(a), "l"(b)); return d;
}
__device__ __forceinline__ ull dup2(float x) {
    ull d; asm("mov.b64 %0,{%1,%1};" : "=l"(d) : "f"(x)); return d;
}
__device__ __forceinline__ float2 unpk(ull a) {
    float2 r; asm("mov.b64 {%0,%1},%2;" : "=f"(r.x), "=f"(r.y) : "l"(a)); return r;
}
__device__ __forceinline__ ull pk(float x, float y) {
    ull d; asm("mov.b64 %0,{%1,%2};" : "=l"(d) : "f"(x), "f"(y)); return d;
}
__device__ __forceinline__ float frcp(float x) {
    float r; asm("rcp.approx.f32 %0,%1;" : "=f"(r) : "f"(x)); return r;
}

// ---------------------------------------------------------------------------
// Kernel 1: grid = 128 blocks (64 row-tiles x 2 mats), 512 threads, <=1
// block/SM (zero raggedness). Tile = 32 rows. FFMA2 packed over k-pairs.
// mat 0 -> g_Ea row-major (coalesced STG). mat 1 -> g_EcT via smem transpose.
// ---------------------------------------------------------------------------
#define W_STRIDE 132
#define K1_SMEM ((DIM * W_STRIDE + 32 * DIM) * 4)   // 67584 + 16384 = 83968 B

__global__ void __launch_bounds__(512, 1) k1_gemm_exp(
    const float* __restrict__ X,
    const float* __restrict__ W1,
    const float* __restrict__ W2)
{
    extern __shared__ float sm[];
    float* Ws = sm;                        // 128 x 132
    float* Xs = sm + DIM * W_STRIDE;       // 32 x 128

    const int t       = threadIdx.x;
    const int mat     = blockIdx.x & 1;
    const int rowbase = (blockIdx.x >> 1) * 32;
    const float* W = mat ? W2 : W1;

    #pragma unroll
    for (int i = t; i < DIM * 32; i += 512) {           // W: 4096 float4
        int m  = i >> 5;
        int k4 = i & 31;
        *(float4*)&Ws[m * W_STRIDE + k4 * 4] = ((const float4*)W)[i];
    }
    #pragma unroll
    for (int i = t; i < 1024; i += 512)                 // X: 32 rows
        ((float4*)Xs)[i] = ((const float4*)X)[rowbase * 32 + i];
    __syncthreads();

    const int m  = t & 127;
    const int r0 = (t >> 7) * 8;            // uniform per warp -> X broadcast

    ull acc[8];
    #pragma unroll
    for (int r = 0; r < 8; r++) acc[r] = dup2(0.0f);

    #pragma unroll 4
    for (int k4 = 0; k4 < 32; k4++) {
        ulonglong2 w = *(const ulonglong2*)&Ws[m * W_STRIDE + k4 * 4];
        #pragma unroll
        for (int r = 0; r < 8; r++) {
            ulonglong2 x = *(const ulonglong2*)&Xs[(r0 + r) * DIM + k4 * 4];
            acc[r] = fma2(w.x, x.x, acc[r]);
            acc[r] = fma2(w.y, x.y, acc[r]);
        }
    }

    float val[8];
    #pragma unroll
    for (int r = 0; r < 8; r++) {
        float2 a = unpk(acc[r]);
        val[r] = __expf(2.0f * (a.x + a.y));
    }

    if (mat == 0) {
        #pragma unroll
        for (int r = 0; r < 8; r++)                     // lanes m -> coalesced
            g_Ea[(size_t)(rowbase + r0 + r) * DIM + m] = val[r];
    } else {
        // smem transpose (reuse Ws region: need 128*33 floats <= 128*132)
        float* Es = Ws;
        __syncthreads();
        #pragma unroll
        for (int r = 0; r < 8; r++)
            Es[m * 33 + (r0 + r)] = val[r];             // (m+r)%32 banks: CF
        __syncthreads();
        const int b  = rowbase >> 8;
        const int d0 = rowbase & 255;
        #pragma unroll
        for (int it = 0; it < 2; it++) {
            int vi = t + it * 512;                      // 1024 float4 total
            int mm = vi >> 3;
            int dq = vi & 7;
            float4 o;
            o.x = Es[mm * 33 + dq * 4 + 0];
            o.y = Es[mm * 33 + dq * 4 + 1];
            o.z = Es[mm * 33 + dq * 4 + 2];
            o.w = Es[mm * 33 + dq * 4 + 3];
            *(float4*)&g_EcT[(size_t)(b * DIM + mm) * DD + d0 + dq * 4] = o;
        }
    }
}

// ---------------------------------------------------------------------------
// Kernel 2: grid = 1024 (8b x 64 j-groups x 2 k-tiles), 128 threads.
// Thread = 1 k, 4 j (two packed f32x2 j-pairs). Ec read straight from L2
// (coalesced LDG, reg double-buffered). 4-way rational combine: 1 rcp / 4 m.
// Per 4m x 4j (16 elems): 28 FMA2 + 4 RCP + 8 LDS + 4 LDG + ~10 MOV.
// ---------------------------------------------------------------------------
__global__ void __launch_bounds__(128, 6) k2_pairwise(
    const float* __restrict__ v,
    float* __restrict__ out)
{
    __shared__ __align__(16) float  EaTf[DIM * 4];   // [m][j], j-pairs at 8B
    __shared__ __align__(16) float2 vD[DIM];         // duplicated v

    const int t  = threadIdx.x;
    const int bid = blockIdx.x;
    const int kt = bid & 1;
    const int jg = (bid >> 1) & 63;
    const int b  = bid >> 7;
    const int j0 = jg * 4;
    const int k  = kt * 128 + t;

    // Stage EaT (transpose 4 x 128) and duplicated v.
    #pragma unroll
    for (int it = 0; it < 4; it++) {
        int i = t + it * 128;
        int j = i & 3, mm = i >> 2;
        EaTf[mm * 4 + j] = g_Ea[(size_t)(b * DD + j0 + j) * DIM + mm];
    }
    {
        float vv = v[t];
        vD[t] = make_float2(vv, vv);
    }
    __syncthreads();

    float Vsum = 0.0f;
    #pragma unroll 16
    for (int m4 = 0; m4 < 64; m4++) {
        float4 q = ((const float4*)vD)[m4];
        Vsum += q.x + q.z;
    }

    const ull ONE2 = dup2(1.0f);
    ull acc0 = dup2(0.0f), acc1 = dup2(0.0f);

    const float* ecp = g_EcT + (size_t)b * DIM * DD + k;   // m-stride = 256
    float e0 = ecp[0], e1 = ecp[256], e2 = ecp[512], e3 = ecp[768];

    #pragma unroll 4
    for (int g = 0; g < 32; g++) {
        const float* np = ecp + (g + 1) * 1024;   // padded tail: safe @ g=31
        float f0 = np[0], f1 = np[256], f2 = np[512], f3 = np[768];

        ull ec0 = dup2(e0), ec1 = dup2(e1), ec2 = dup2(e2), ec3 = dup2(e3);
        ulonglong2 vab = *(const ulonglong2*)&vD[4 * g];       // (v0v0,v1v1)
        ulonglong2 vcd = *(const ulonglong2*)&vD[4 * g + 2];   // (v2v2,v3v3)
        const float* eb = EaTf + 16 * g;

        #pragma unroll
        for (int p = 0; p < 2; p++) {
            ull a0 = *(const ull*)(eb +      2 * p);    // broadcast LDS.64
            ull a1 = *(const ull*)(eb + 4  + 2 * p);
            ull a2 = *(const ull*)(eb + 8  + 2 * p);
            ull a3 = *(const ull*)(eb + 12 + 2 * p);
            ull q0 = fma2(a0, ec0, ONE2);
            ull q1 = fma2(a1, ec1, ONE2);
            ull q2 = fma2(a2, ec2, ONE2);
            ull q3 = fma2(a3, ec3, ONE2);
            ull d01 = mul2(q0, q1);
            ull d23 = mul2(q2, q3);
            ull n01 = mul2(vab.x, q1); n01 = fma2(vab.y, q0, n01);
            ull n23 = mul2(vcd.x, q3); n23 = fma2(vcd.y, q2, n23);
            ull den = mul2(d01, d23);
            ull num = mul2(n01, d23); num = fma2(n23, d01, num);
            float2 dd = unpk(den);
            ull rr  = pk(frcp(dd.x), frcp(dd.y));       // 1 rcp per 2 m
            if (p == 0) acc0 = fma2(num, rr, acc0);
            else        acc1 = fma2(num, rr, acc1);
        }
        e0 = f0; e1 = f1; e2 = f2; e3 = f3;
    }

    float* obase = out + (size_t)(b * DD + j0) * DD + k;
    float2 a0 = unpk(acc0), a1 = unpk(acc1);
    obase[0 * DD] = fmaf(-2.0f, a0.x, Vsum);
    obase[1 * DD] = fmaf(-2.0f, a0.y, Vsum);
    obase[2 * DD] = fmaf(-2.0f, a1.x, Vsum);
    obase[3 * DD] = fmaf(-2.0f, a1.y, Vsum);
}

// ---------------------------------------------------------------------------
extern "C" void kernel_launch(void* const* d_in, const int* in_sizes, int n_in,
                              void* d_out, int out_size)
{
    const float* X  = (const float*)d_in[0];
    const float* W1 = (const float*)d_in[1];
    const float* W2 = (const float*)d_in[2];
    const float* v  = (const float*)d_in[3];
    float* out      = (float*)d_out;

    cudaFuncSetAttribute(k1_gemm_exp,
                         cudaFuncAttributeMaxDynamicSharedMemorySize, K1_SMEM);

    k1_gemm_exp<<<128, 512, K1_SMEM>>>(X, W1, W2);
    k2_pairwise<<<1024, 128>>>(v, out);
}